// round 7
// baseline (speedup 1.0000x reference)
#include <cuda_runtime.h>
#include <cuda_bf16.h>

#define B_ 64
#define T_ 1024
#define I_ 8
#define H_ 512
#define O_ 2
#define NOISE_STD_ 0.05f
#define ALPHA_ 0.2f

#define NT_  256            // 8 warps
#define UPT_ 2              // hidden units per thread
#define NW_  8

#define SA_      8192.0f    // 2^13 fixed-point scale for recurrence dots
#define SO_      2097152.0f // 2^21 fixed-point scale for output dots
#define MAGIC_F  12582912.0f    // 2^23 + 2^22 : round-to-int bias
// Each warp-sum = 32*0x4B400000 + Si (mod 2^32) = 0x68000000 + Si.
// 8 warps: total bias = 8*0x68000000 mod 2^32 = 0x40000000.
// Re-bias to float: add 0x4B400000 - 0x40000000 = 0x0B400000.
#define REBIAS_I ((int)0x0B400000)

// Single-MUFU tanh (~6e-4 rel err; net kernel rel_err ~1e-5).
__device__ __forceinline__ float tanh_mufu(float x) {
    float r; asm("tanh.approx.f32 %0, %1;" : "=f"(r) : "f"(x)); return r;
}

// Warp-wide integer add-reduction (s32 redux supported on sm_103).
__device__ __forceinline__ int redux_add_s32(int v) {
    int r; asm("redux.sync.add.s32 %0, %1, 0xffffffff;" : "=r"(r) : "r"(v)); return r;
}

__global__ __launch_bounds__(NT_, 1)
void lowrank_rnn_kernel(const float* __restrict__ input,   // (B,T,I)
                        const float* __restrict__ noise,   // (B,T,H)
                        const float* __restrict__ wi,      // (I,H)
                        const float* __restrict__ si,      // (I,)
                        const float* __restrict__ m,       // (H,R)
                        const float* __restrict__ n,       // (H,R)
                        const float* __restrict__ wo,      // (H,O)
                        const float* __restrict__ so,      // (O,)
                        const float* __restrict__ h0,      // (H,)
                        float* __restrict__ out,           // (B,T,O)
                        float* __restrict__ traj)          // (B,T,H)
{
    __shared__ float s_in[T_ * I_];          // 32 KB: full input row for this batch
    __shared__ int2  s_a[2][NW_];            // biased a-partials per warp, dbl-buffered
    __shared__ int2  s_o[2][NW_];            // o-partials per warp, dbl-buffered

    const int b    = blockIdx.x;
    const int tid  = threadIdx.x;
    const int warp = tid >> 5;
    const int lane = tid & 31;
    const int k0   = tid * UPT_;

    // ---- stage input into smem, coalesced float4 ----
    {
        const float4* gin  = (const float4*)(input + (size_t)b * T_ * I_);
        float4*       sin4 = (float4*)s_in;
        #pragma unroll
        for (int i = 0; i < (T_ * I_ / 4) / NT_; ++i)     // 8 iters
            sin4[tid + i * NT_] = gin[tid + i * NT_];
    }

    // ---- per-thread weights (constants folded) ----
    float wif[I_][UPT_];                    // wi*si*alpha
    #pragma unroll
    for (int i = 0; i < I_; ++i) {
        const float2 w = *(const float2*)(wi + i * H_ + k0);
        const float  s = si[i] * ALPHA_;
        wif[i][0] = w.x * s; wif[i][1] = w.y * s;
    }
    const float cm  = (ALPHA_ / (float)H_) / SA_;   // alpha/H and 1/Sa into m
    const float so0 = (so[0] / (float)H_) * SO_;    // 1/H and So into wo
    const float so1 = (so[1] / (float)H_) * SO_;
    float m0f[UPT_], m1f[UPT_], n0f[UPT_], n1f[UPT_], wo0f[UPT_], wo1f[UPT_];
    float negmc[UPT_];   // -(MAGIC_F)*(m0f+m1f): cancels bias carried in A0b,A1b
    {
        const float4 mm = *(const float4*)(m  + k0 * 2);  // m[k0][0..1], m[k0+1][0..1]
        const float4 nn = *(const float4*)(n  + k0 * 2);
        const float4 ww = *(const float4*)(wo + k0 * 2);
        m0f[0] = mm.x * cm;  m1f[0] = mm.y * cm;
        m0f[1] = mm.z * cm;  m1f[1] = mm.w * cm;
        n0f[0] = nn.x * SA_; n1f[0] = nn.y * SA_;
        n0f[1] = nn.z * SA_; n1f[1] = nn.w * SA_;
        wo0f[0] = ww.x * so0; wo1f[0] = ww.y * so1;
        wo0f[1] = ww.z * so0; wo1f[1] = ww.w * so1;
        negmc[0] = -MAGIC_F * (m0f[0] + m1f[0]);
        negmc[1] = -MAGIC_F * (m0f[1] + m1f[1]);
    }

    float h[UPT_];
    { const float2 hh = *(const float2*)(h0 + k0); h[0] = hh.x; h[1] = hh.y; }

    const float* nz_base   = noise + (size_t)b * T_ * H_ + k0;
    float*       traj_base = traj  + (size_t)b * T_ * H_ + k0;
    float*       out_base  = out   + (size_t)b * T_ * O_;

    // ---- noise prefetch ring, depth 4 ----
    float2 ring[4];
    #pragma unroll
    for (int j = 0; j < 4; ++j)
        ring[j] = *(const float2*)(nz_base + (size_t)j * H_);

    // ---- prologue: biased a(0) from r = tanh(h0); hb(0) after the barrier ----
    float A0b, A1b;     // biased recurrence dots (carry +MAGIC_F each)
    float hb[UPT_];     // hb(t) = 0.8h + 0.05nz + alpha*p + negmc
    {
        const float r0 = tanh_mufu(h[0]);
        const float r1 = tanh_mufu(h[1]);
        const float pa0 = fmaf(r1, n0f[1], r0 * n0f[0]);
        const float pa1 = fmaf(r1, n1f[1], r0 * n1f[0]);
        const int W0 = redux_add_s32(__float_as_int(pa0 + MAGIC_F));
        const int W1 = redux_add_s32(__float_as_int(pa1 + MAGIC_F));
        if (lane == 0) s_a[1][warp] = make_int2(W0, W1);   // slot 1: loop t=0 uses slot 0
        __syncthreads();   // covers s_in staging + prologue partials

        const int4* va = (const int4*)s_a[1];
        const int4 v0 = va[0], v1 = va[1], v2 = va[2], v3 = va[3];
        const int sx = ((v0.x + v0.z) + (v1.x + v1.z)) + ((v2.x + v2.z) + (v3.x + v3.z));
        const int sy = ((v0.y + v0.w) + (v1.y + v1.w)) + ((v2.y + v2.w) + (v3.y + v3.w));
        A0b = __int_as_float(sx + REBIAS_I);
        A1b = __int_as_float(sy + REBIAS_I);

        const float4 j0 = *(const float4*)(s_in + 0);
        const float4 j1 = *(const float4*)(s_in + 4);
        const float2 nz = ring[0];
        const float nza[UPT_] = {nz.x, nz.y};
        #pragma unroll
        for (int u = 0; u < UPT_; ++u) {
            float pp = fmaf(j0.x, wif[0][u], negmc[u]);
            pp = fmaf(j0.y, wif[1][u], pp);
            pp = fmaf(j0.z, wif[2][u], pp);
            pp = fmaf(j0.w, wif[3][u], pp);
            pp = fmaf(j1.x, wif[4][u], pp);
            pp = fmaf(j1.y, wif[5][u], pp);
            pp = fmaf(j1.z, wif[6][u], pp);
            pp = fmaf(j1.w, wif[7][u], pp);
            pp = fmaf(NOISE_STD_, nza[u], pp);
            hb[u] = fmaf(1.0f - ALPHA_, h[u], pp);
        }
    }

    // ---- main scan ----
    #pragma unroll 4
    for (int t = 0; t < T_; ++t) {
        const int buf = t & 1;

        // ======== CRITICAL PATH ========
        float hx0 = fmaf(A1b, m1f[0], fmaf(A0b, m0f[0], hb[0]));
        float hx1 = fmaf(A1b, m1f[1], fmaf(A0b, m0f[1], hb[1]));
        const float r0 = tanh_mufu(hx0);
        const float r1 = tanh_mufu(hx1);
        const float pa0 = fmaf(r1, n0f[1], r0 * n0f[0]);
        const float pa1 = fmaf(r1, n1f[1], r0 * n1f[0]);
        const int W0 = redux_add_s32(__float_as_int(pa0 + MAGIC_F));
        const int W1 = redux_add_s32(__float_as_int(pa1 + MAGIC_F));
        if (lane == 0) s_a[buf][warp] = make_int2(W0, W1);

        // ======== SHADOW (overlaps REDUX/barrier latency) ========
        {   // o-dots
            const float po0 = fmaf(r1, wo0f[1], r0 * wo0f[0]);
            const float po1 = fmaf(r1, wo1f[1], r0 * wo1f[0]);
            const int U0 = redux_add_s32(__float2int_rn(po0));
            const int U1 = redux_add_s32(__float2int_rn(po1));
            if (lane == 0) s_o[buf][warp] = make_int2(U0, U1);
        }
        // traj[t] = h_{t+1}, coalesced STG.64
        *(float2*)(traj_base + (size_t)t * H_) = make_float2(hx0, hx1);
        // noise prefetch t+4
        {
            int tp = t + 4; if (tp > T_ - 1) tp = T_ - 1;
            ring[t & 3] = *(const float2*)(nz_base + (size_t)tp * H_);
        }
        // hb(t+1)
        {
            const int tn = (t + 1 < T_) ? t + 1 : t;
            const float4 j0 = *(const float4*)(s_in + tn * I_);
            const float4 j1 = *(const float4*)(s_in + tn * I_ + 4);
            const float2 nz = ring[(t + 1) & 3];
            const float nza[UPT_] = {nz.x, nz.y};
            const float hxa[UPT_] = {hx0, hx1};
            #pragma unroll
            for (int u = 0; u < UPT_; ++u) {
                float pp = fmaf(j0.x, wif[0][u], negmc[u]);
                pp = fmaf(j0.y, wif[1][u], pp);
                pp = fmaf(j0.z, wif[2][u], pp);
                pp = fmaf(j0.w, wif[3][u], pp);
                pp = fmaf(j1.x, wif[4][u], pp);
                pp = fmaf(j1.y, wif[5][u], pp);
                pp = fmaf(j1.z, wif[6][u], pp);
                pp = fmaf(j1.w, wif[7][u], pp);
                pp = fmaf(NOISE_STD_, nza[u], pp);
                hb[u] = fmaf(1.0f - ALPHA_, hxa[u], pp);
            }
        }

        __syncthreads();   // one bar per step

        // combine a-partials (8 warps, magic re-bias: no I2F on the path)
        {
            const int4* va = (const int4*)s_a[buf];
            const int4 v0 = va[0], v1 = va[1], v2 = va[2], v3 = va[3];
            const int sx = ((v0.x + v0.z) + (v1.x + v1.z)) + ((v2.x + v2.z) + (v3.x + v3.z));
            const int sy = ((v0.y + v0.w) + (v1.y + v1.w)) + ((v2.y + v2.w) + (v3.y + v3.w));
            A0b = __int_as_float(sx + REBIAS_I);
            A1b = __int_as_float(sy + REBIAS_I);
        }

        // out[t] (tid 0 only; its extra work hides under next step's shadow)
        if (tid == 0) {
            const int4* vo = (const int4*)s_o[buf];
            const int4 v0 = vo[0], v1 = vo[1], v2 = vo[2], v3 = vo[3];
            const int sx = ((v0.x + v0.z) + (v1.x + v1.z)) + ((v2.x + v2.z) + (v3.x + v3.z));
            const int sy = ((v0.y + v0.w) + (v1.y + v1.w)) + ((v2.y + v2.w) + (v3.y + v3.w));
            const float o0 = (float)sx * (1.0f / SO_);
            const float o1 = (float)sy * (1.0f / SO_);
            *(float2*)(out_base + (size_t)t * O_) = make_float2(o0, o1);
        }
    }
}

extern "C" void kernel_launch(void* const* d_in, const int* in_sizes, int n_in,
                              void* d_out, int out_size) {
    const float* input = (const float*)d_in[0];
    const float* noise = (const float*)d_in[1];
    const float* wi    = (const float*)d_in[2];
    const float* si    = (const float*)d_in[3];
    const float* m     = (const float*)d_in[4];
    const float* n     = (const float*)d_in[5];
    const float* wo    = (const float*)d_in[6];
    const float* so    = (const float*)d_in[7];
    const float* h0    = (const float*)d_in[8];

    float* out  = (float*)d_out;                         // (B,T,O) first
    float* traj = (float*)d_out + (size_t)B_ * T_ * O_;  // then (B,T,H)

    lowrank_rnn_kernel<<<B_, NT_>>>(input, noise, wi, si, m, n, wo, so, h0,
                                    out, traj);
}

// round 8
// speedup vs baseline: 1.0800x; 1.0800x over previous
#include <cuda_runtime.h>
#include <cuda_bf16.h>

#define B_ 64
#define T_ 1024
#define I_ 8
#define H_ 512
#define O_ 2
#define NOISE_STD_ 0.05f
#define ALPHA_ 0.2f

#define NT_   256           // 2 groups x 128 threads
#define GSZ_  128           // threads per group
#define UPT_  4             // hidden units per thread (GSZ_*UPT_ == H_)
#define NW_   4             // warps per group

#define SA_   131072.0f     // 2^17 fixed-point scale for recurrence dots (R4 exact)
#define SO_   2097152.0f    // 2^21 fixed-point scale for output dots

// Single-MUFU tanh (~6e-4 rel err; net kernel rel_err ~1e-5, traj-dominated).
__device__ __forceinline__ float tanh_mufu(float x) {
    float r; asm("tanh.approx.f32 %0, %1;" : "=f"(r) : "f"(x)); return r;
}

// Warp-wide integer add-reduction (s32 redux supported on sm_103).
__device__ __forceinline__ int redux_add_s32(int v) {
    int r; asm("redux.sync.add.s32 %0, %1, 0xffffffff;" : "=r"(r) : "r"(v)); return r;
}

// Group-local barrier: named barrier over 128 threads (ids 1 and 2).
__device__ __forceinline__ void gbar(int g) {
    asm volatile("bar.sync %0, 128;" :: "r"(g + 1) : "memory");
}

__global__ __launch_bounds__(NT_, 1)
void lowrank_rnn_kernel(const float* __restrict__ input,   // (B,T,I)
                        const float* __restrict__ noise,   // (B,T,H)
                        const float* __restrict__ wi,      // (I,H)
                        const float* __restrict__ si,      // (I,)
                        const float* __restrict__ m,       // (H,R)
                        const float* __restrict__ n,       // (H,R)
                        const float* __restrict__ wo,      // (H,O)
                        const float* __restrict__ so,      // (O,)
                        const float* __restrict__ h0,      // (H,)
                        float* __restrict__ out,           // (B,T,O)
                        float* __restrict__ traj)          // (B,T,H)
{
    __shared__ int4 s_red[2][2][NW_];        // [group][buf][warp] = (a0,a1,o0,o1)

    const int tid  = threadIdx.x;
    const int g    = tid >> 7;               // group (0/1) = batch within CTA
    const int gtid = tid & (GSZ_ - 1);
    const int warp = gtid >> 5;
    const int lane = gtid & 31;
    const int k0   = gtid * UPT_;
    const int b    = blockIdx.x * 2 + g;

    // ---- per-thread weights (folded constants, identical to R4) ----
    float wif[I_][UPT_];
    #pragma unroll
    for (int i = 0; i < I_; ++i) {
        const float4 w = *(const float4*)(wi + i * H_ + k0);
        const float  s = si[i];
        wif[i][0] = w.x * s; wif[i][1] = w.y * s;
        wif[i][2] = w.z * s; wif[i][3] = w.w * s;
    }
    const float cm  = (ALPHA_ / (float)H_) / SA_;  // alpha/H and 1/Sa folded into m
    const float so0 = (so[0] / (float)H_) * SO_;   // 1/H and So folded into wo
    const float so1 = (so[1] / (float)H_) * SO_;
    float m0f[UPT_], m1f[UPT_], n0f[UPT_], n1f[UPT_], wo0f[UPT_], wo1f[UPT_];
    #pragma unroll
    for (int j = 0; j < UPT_; ++j) {
        const int k = k0 + j;
        m0f[j]  = m[k * 2 + 0] * cm;        m1f[j]  = m[k * 2 + 1] * cm;
        n0f[j]  = n[k * 2 + 0] * SA_;       n1f[j]  = n[k * 2 + 1] * SA_;
        wo0f[j] = wo[k * 2 + 0] * so0;      wo1f[j] = wo[k * 2 + 1] * so1;
    }

    float h[UPT_];
    {
        const float4 hh = *(const float4*)(h0 + k0);
        h[0] = hh.x; h[1] = hh.y; h[2] = hh.z; h[3] = hh.w;
    }

    const float* nz_base   = noise + (size_t)b * T_ * H_ + k0;
    const float* in_base   = input + (size_t)b * T_ * I_;
    float*       traj_base = traj  + (size_t)b * T_ * H_ + k0;
    float*       out_base  = out   + (size_t)b * T_ * O_;

    // ---- prefetch rings, depth 4: noise (per-thread) + input row (broadcast) ----
    float4 ring[4];                // noise
    float4 ir0[4], ir1[4];         // input row halves (uniform across group)
    #pragma unroll
    for (int j = 0; j < 4; ++j) {
        ring[j] = *(const float4*)(nz_base + (size_t)j * H_);
        ir0[j]  = *(const float4*)(in_base + j * I_);
        ir1[j]  = *(const float4*)(in_base + j * I_ + 4);
    }

    // ---- pre-loop: a = n^T r_0 (buffer 1; loop iter 0 reads buffer 0) ----
    float a0, a1;
    {
        float pa0 = 0.0f, pa1 = 0.0f;
        #pragma unroll
        for (int u = 0; u < UPT_; ++u) {
            const float r = tanh_mufu(h[u]);
            pa0 = fmaf(r, n0f[u], pa0);
            pa1 = fmaf(r, n1f[u], pa1);
        }
        const int ia0 = redux_add_s32(__float2int_rn(pa0));
        const int ia1 = redux_add_s32(__float2int_rn(pa1));
        if (lane == 0) s_red[g][1][warp] = make_int4(ia0, ia1, 0, 0);
        gbar(g);
        int sx = 0, sy = 0;
        #pragma unroll
        for (int w = 0; w < NW_; ++w) {
            const int4 v = s_red[g][1][w];
            sx += v.x; sy += v.y;
        }
        a0 = (float)sx; a1 = (float)sy;  // 1/Sa folded into m0f/m1f
    }

    // ---- main scan (R4 body; input from ring instead of smem) ----
    #pragma unroll 4
    for (int t = 0; t < T_; ++t) {
        const int j = t & 3;
        const float4 nz = ring[j];
        const float4 i0 = ir0[j];
        const float4 i1 = ir1[j];
        int tp = t + 4; if (tp > T_ - 1) tp = T_ - 1;            // clamp tail
        ring[j] = *(const float4*)(nz_base + (size_t)tp * H_);   // prefetch t+4
        ir0[j]  = *(const float4*)(in_base + tp * I_);
        ir1[j]  = *(const float4*)(in_base + tp * I_ + 4);

        // input projection p_t for 4 units (off critical path)
        float p[UPT_];
        #pragma unroll
        for (int u = 0; u < UPT_; ++u) {
            float pp = i0.x * wif[0][u];
            pp = fmaf(i0.y, wif[1][u], pp);
            pp = fmaf(i0.z, wif[2][u], pp);
            pp = fmaf(i0.w, wif[3][u], pp);
            pp = fmaf(i1.x, wif[4][u], pp);
            pp = fmaf(i1.y, wif[5][u], pp);
            pp = fmaf(i1.z, wif[6][u], pp);
            pp = fmaf(i1.w, wif[7][u], pp);
            p[u] = pp;
        }
        const float nza[UPT_] = {nz.x, nz.y, nz.z, nz.w};

        // h' = 0.8h + 0.05nz + 0.2p + a0*m0f + a1*m1f ; r' = tanh(h')
        float pa0 = 0.0f, pa1 = 0.0f, po0 = 0.0f, po1 = 0.0f;
        #pragma unroll
        for (int u = 0; u < UPT_; ++u) {
            const float base = fmaf(NOISE_STD_, nza[u], ALPHA_ * p[u]);  // off path
            const float hb   = fmaf(1.0f - ALPHA_, h[u], base);          // off path
            float hx = fmaf(a0, m0f[u], hb);                             // path: 2 FMA
            hx       = fmaf(a1, m1f[u], hx);
            h[u] = hx;
            const float r = tanh_mufu(hx);                               // 1 MUFU
            pa0 = fmaf(r, n0f[u], pa0);     // scaled by Sa
            pa1 = fmaf(r, n1f[u], pa1);
            po0 = fmaf(r, wo0f[u], po0);    // scaled by So
            po1 = fmaf(r, wo1f[u], po1);
        }

        // traj[t] = h_{t+1}, coalesced STG.128
        *(float4*)(traj_base + (size_t)t * H_) = make_float4(h[0], h[1], h[2], h[3]);

        // fixed-point warp reduction: one REDUX per value (a-pair on crit path)
        const int ia0 = redux_add_s32(__float2int_rn(pa0));
        const int ia1 = redux_add_s32(__float2int_rn(pa1));
        const int io0 = redux_add_s32(__float2int_rn(po0));
        const int io1 = redux_add_s32(__float2int_rn(po1));

        const int buf = t & 1;
        if (lane == 0) s_red[g][buf][warp] = make_int4(ia0, ia1, io0, io1);
        gbar(g);                          // one group barrier per step

        // tiny cross-warp integer sum (4 partials), redundant per-thread
        const int4 v0 = s_red[g][buf][0];
        const int4 v1 = s_red[g][buf][1];
        const int4 v2 = s_red[g][buf][2];
        const int4 v3 = s_red[g][buf][3];
        a0 = (float)((v0.x + v1.x) + (v2.x + v3.x));
        a1 = (float)((v0.y + v1.y) + (v2.y + v3.y));

        if (gtid == 0) {
            const float o0 = (float)((v0.z + v1.z) + (v2.z + v3.z)) * (1.0f / SO_);
            const float o1 = (float)((v0.w + v1.w) + (v2.w + v3.w)) * (1.0f / SO_);
            *(float2*)(out_base + (size_t)t * O_) = make_float2(o0, o1);
        }
    }
}

extern "C" void kernel_launch(void* const* d_in, const int* in_sizes, int n_in,
                              void* d_out, int out_size) {
    const float* input = (const float*)d_in[0];
    const float* noise = (const float*)d_in[1];
    const float* wi    = (const float*)d_in[2];
    const float* si    = (const float*)d_in[3];
    const float* m     = (const float*)d_in[4];
    const float* n     = (const float*)d_in[5];
    const float* wo    = (const float*)d_in[6];
    const float* so    = (const float*)d_in[7];
    const float* h0    = (const float*)d_in[8];

    float* out  = (float*)d_out;                         // (B,T,O) first
    float* traj = (float*)d_out + (size_t)B_ * T_ * O_;  // then (B,T,H)

    lowrank_rnn_kernel<<<B_ / 2, NT_>>>(input, noise, wi, si, m, n, wo, so, h0,
                                        out, traj);
}